// round 2
// baseline (speedup 1.0000x reference)
#include <cuda_runtime.h>
#include <cuda_bf16.h>
#include <math.h>

// Problem constants (fixed by reference setup_inputs)
#define BB 8
#define TT 16
#define CC 64
#define NN 4096          // H*W
#define KSEL 2048        // keep_k = N*(1-0.5)

// Scratch (device globals — no allocation allowed)
__device__ float g_partial[BB * TT * NN];            // sqrt(sum_c x^2) per (b,t,n), 2 MB
__device__ unsigned g_maskbits[BB * (NN / 32)];      // 1 bit per (b,n), 4 KB

// ---------------------------------------------------------------------------
// Kernel 1: per-(b,t,n) partial = sqrt(sum_c x[b,t,c,n]^2), float4 over n.
// Each thread owns 4 consecutive n; 64 float4 loads at stride N, unroll 8
// for MLP. Sum over c is sequential ascending (bit-exact vs R1, rel_err=0).
// ---------------------------------------------------------------------------
__global__ void __launch_bounds__(256) k_partial(const float4* __restrict__ x) {
    int idx = blockIdx.x * 256 + threadIdx.x;          // [0, B*T*N/4)
    int n4 = idx & (NN / 4 - 1);
    int bt = idx >> 10;                                // b*T + t
    const float4* p = x + (size_t)bt * CC * (NN / 4) + n4;
    float a0 = 0.f, a1 = 0.f, a2 = 0.f, a3 = 0.f;
#pragma unroll 8
    for (int c = 0; c < CC; ++c) {
        float4 v = p[(size_t)c * (NN / 4)];
        a0 += v.x * v.x;
        a1 += v.y * v.y;
        a2 += v.z * v.z;
        a3 += v.w * v.w;
    }
    float4 r;
    r.x = sqrtf(a0); r.y = sqrtf(a1); r.z = sqrtf(a2); r.w = sqrtf(a3);
    ((float4*)g_partial)[idx] = r;
}

// ---------------------------------------------------------------------------
// Kernel 2: per-batch exact top-K -> mask bits. 1024 threads/block, 1 block
// per batch. 2-bit radix select with forced-bit skipping (OR==AND) and a
// single __syncthreads per active iteration.
// ---------------------------------------------------------------------------
__global__ void __launch_bounds__(1024, 1) k_select() {
    __shared__ unsigned long long s_acc[20];   // per-iteration packed counters
    __shared__ unsigned s_u32[66];             // OR/AND reduction
    __shared__ unsigned s_mask[NN / 32];       // 128 words
    __shared__ int s_scan[32];

    const int b    = blockIdx.x;
    const int j    = threadIdx.x;              // 0..1023
    const int lane = j & 31;
    const int wid  = j >> 5;

    // --- scores: 4 per thread, sequential over t (bit-exact order) ---
    const float4* part = (const float4*)g_partial;
    float s0 = 0.f, s1 = 0.f, s2 = 0.f, s3 = 0.f;
#pragma unroll
    for (int t = 0; t < TT; ++t) {
        float4 f = part[(size_t)(b * TT + t) * (NN / 4) + j];
        s0 += f.x; s1 += f.y; s2 += f.z; s3 += f.w;
    }
    const float inv = 1.0f / (float)TT;
    unsigned u0 = __float_as_uint(s0 * inv);
    unsigned u1 = __float_as_uint(s1 * inv);
    unsigned u2 = __float_as_uint(s2 * inv);
    unsigned u3 = __float_as_uint(s3 * inv);

    // --- init shared ---
    if (j < 20) s_acc[j] = 0ull;
    if (j < NN / 32) s_mask[j] = 0u;

    // --- block OR / AND of all score bits ---
    unsigned ov = u0 | u1 | u2 | u3;
    unsigned av = u0 & u1 & u2 & u3;
#pragma unroll
    for (int d = 16; d; d >>= 1) {
        ov |= __shfl_xor_sync(0xffffffffu, ov, d);
        av &= __shfl_xor_sync(0xffffffffu, av, d);
    }
    if (lane == 0) { s_u32[wid] = ov; s_u32[32 + wid] = av; }
    __syncthreads();
    if (wid == 0) {
        unsigned o2 = s_u32[lane], a2 = s_u32[32 + lane];
#pragma unroll
        for (int d = 16; d; d >>= 1) {
            o2 |= __shfl_xor_sync(0xffffffffu, o2, d);
            a2 &= __shfl_xor_sync(0xffffffffu, a2, d);
        }
        if (lane == 0) { s_u32[64] = o2; s_u32[65] = a2; }
    }
    __syncthreads();
    const unsigned orv  = s_u32[64];
    const unsigned andv = s_u32[65];
    const unsigned diff = orv ^ andv;

    // --- 2-bit radix select: largest thr with count(u >= thr) >= KSEL ---
    unsigned thr = 0u;
#pragma unroll
    for (int p = 15; p >= 0; --p) {
        unsigned m2 = 3u << (2 * p);
        if ((diff & m2) == 0u) {               // both bits forced (uniform)
            thr |= (andv & m2);
            continue;
        }
        unsigned c1 = thr | (1u << (2 * p));
        unsigned c2 = thr | (2u << (2 * p));
        unsigned c3 = thr | (3u << (2 * p));
        int n1 = (u0 >= c1) + (u1 >= c1) + (u2 >= c1) + (u3 >= c1);
        int n2 = (u0 >= c2) + (u1 >= c2) + (u2 >= c2) + (u3 >= c2);
        int n3 = (u0 >= c3) + (u1 >= c3) + (u2 >= c3) + (u3 >= c3);
        unsigned long long pk = (unsigned long long)n1
                              | ((unsigned long long)n2 << 20)
                              | ((unsigned long long)n3 << 40);
#pragma unroll
        for (int d = 16; d; d >>= 1) pk += __shfl_xor_sync(0xffffffffu, pk, d);
        if (lane == 0) atomicAdd(&s_acc[p], pk);
        __syncthreads();
        unsigned long long tot = s_acc[p];
        int N1 = (int)(tot & 0xFFFFFull);
        int N2 = (int)((tot >> 20) & 0xFFFFFull);
        int N3 = (int)((tot >> 40) & 0xFFFFFull);
        if      (N3 >= KSEL) thr = c3;
        else if (N2 >= KSEL) thr = c2;
        else if (N1 >= KSEL) thr = c1;
    }

    // --- strictly-greater count (ties admitted by lowest index) ---
    {
        int gt = (u0 > thr) + (u1 > thr) + (u2 > thr) + (u3 > thr);
        unsigned long long pk = (unsigned long long)gt;
#pragma unroll
        for (int d = 16; d; d >>= 1) pk += __shfl_xor_sync(0xffffffffu, pk, d);
        if (lane == 0) atomicAdd(&s_acc[16], pk);
        __syncthreads();
    }
    int n_greater = (int)(s_acc[16] & 0xFFFFFull);
    int need = KSEL - n_greater;

    // --- exclusive scan over threads of per-thread equal-count ---
    int e = (u0 == thr) + (u1 == thr) + (u2 == thr) + (u3 == thr);
    int v = e;
#pragma unroll
    for (int d = 1; d < 32; d <<= 1) {
        int t = __shfl_up_sync(0xffffffffu, v, d);
        if (lane >= d) v += t;
    }
    if (lane == 31) s_scan[wid] = v;
    __syncthreads();
    if (wid == 0) {
        int w = s_scan[lane];
#pragma unroll
        for (int d = 1; d < 32; d <<= 1) {
            int t = __shfl_up_sync(0xffffffffu, w, d);
            if (lane >= d) w += t;
        }
        s_scan[lane] = w;
    }
    __syncthreads();
    int excl = v - e + (wid ? s_scan[wid - 1] : 0);

    // --- mask nibble for n = 4j..4j+3 ---
    unsigned nib = 0;
    int r = excl;
    unsigned uu[4] = {u0, u1, u2, u3};
#pragma unroll
    for (int i = 0; i < 4; ++i) {
        if (uu[i] > thr) {
            nib |= 1u << i;
        } else if (uu[i] == thr) {
            if (r < need) nib |= 1u << i;
            ++r;
        }
    }
    atomicOr(&s_mask[j >> 3], nib << ((j & 7) * 4));
    __syncthreads();
    if (j < NN / 32) g_maskbits[b * (NN / 32) + j] = s_mask[j];
}

// ---------------------------------------------------------------------------
// Kernel 3: streaming masked copy. 4 float4 (16 floats = 16 n) per thread,
// one mask-word load per thread. REVERSE block order to hit the L2 residue
// left by k_partial; __stcs output writes (evict-first) to protect it.
// ---------------------------------------------------------------------------
__global__ void __launch_bounds__(256) k_mask(const float4* __restrict__ x4,
                                              float4* __restrict__ o4) {
    unsigned blk = gridDim.x - 1 - blockIdx.x;           // reverse traversal
    unsigned i0 = blk * 1024u + ((unsigned)threadIdx.x << 2);  // 4 float4
    int b  = i0 >> 20;                                   // 2^20 float4 / batch
    int n0 = (i0 & (NN / 4 - 1)) << 2;                   // first n (aligned 16)
    unsigned mword = g_maskbits[(b << 7) + (n0 >> 5)];
    unsigned bits  = mword >> (n0 & 31);                 // 16 valid bits

    float4 v0 = x4[i0 + 0];
    float4 v1 = x4[i0 + 1];
    float4 v2 = x4[i0 + 2];
    float4 v3 = x4[i0 + 3];

    v0.x = (bits & 0x0001u) ? v0.x : 0.f;
    v0.y = (bits & 0x0002u) ? v0.y : 0.f;
    v0.z = (bits & 0x0004u) ? v0.z : 0.f;
    v0.w = (bits & 0x0008u) ? v0.w : 0.f;
    v1.x = (bits & 0x0010u) ? v1.x : 0.f;
    v1.y = (bits & 0x0020u) ? v1.y : 0.f;
    v1.z = (bits & 0x0040u) ? v1.z : 0.f;
    v1.w = (bits & 0x0080u) ? v1.w : 0.f;
    v2.x = (bits & 0x0100u) ? v2.x : 0.f;
    v2.y = (bits & 0x0200u) ? v2.y : 0.f;
    v2.z = (bits & 0x0400u) ? v2.z : 0.f;
    v2.w = (bits & 0x0800u) ? v2.w : 0.f;
    v3.x = (bits & 0x1000u) ? v3.x : 0.f;
    v3.y = (bits & 0x2000u) ? v3.y : 0.f;
    v3.z = (bits & 0x4000u) ? v3.z : 0.f;
    v3.w = (bits & 0x8000u) ? v3.w : 0.f;

    __stcs(&o4[i0 + 0], v0);
    __stcs(&o4[i0 + 1], v1);
    __stcs(&o4[i0 + 2], v2);
    __stcs(&o4[i0 + 3], v3);
}

// ---------------------------------------------------------------------------
extern "C" void kernel_launch(void* const* d_in, const int* in_sizes, int n_in,
                              void* d_out, int out_size) {
    const float* x = (const float*)d_in[0];
    float* out = (float*)d_out;

    // Kernel 1: B*T*N/4 = 131072 threads
    k_partial<<<(BB * TT * NN / 4) / 256, 256>>>((const float4*)x);

    // Kernel 2: one 1024-thread block per batch
    k_select<<<BB, 1024>>>();

    // Kernel 3: 8388608 float4 / 4 per thread = 2097152 threads
    k_mask<<<(BB * TT * CC * NN / 16) / 256, 256>>>(
        (const float4*)x, (float4*)out);
}

// round 3
// speedup vs baseline: 1.0241x; 1.0241x over previous
#include <cuda_runtime.h>
#include <cuda_bf16.h>
#include <math.h>

// Problem constants (fixed by reference setup_inputs)
#define BB 8
#define TT 16
#define CC 64
#define NN 4096          // H*W
#define KSEL 2048        // keep_k = N*(1-0.5)

// Scratch (device globals — no allocation allowed)
__device__ float g_partial[BB * TT * NN];            // sqrt(sum_c x^2) per (b,t,n), 2 MB
__device__ unsigned g_maskbits[BB * (NN / 32)];      // 1 bit per (b,n), 4 KB

// ---------------------------------------------------------------------------
// Kernel 1 (R1 form): per-(b,t,n) partial = sqrt(sum_c x[b,t,c,n]^2)
// 524288 threads, each does 64 coalesced scalar loads (stride N between c).
// ---------------------------------------------------------------------------
__global__ void __launch_bounds__(256) k_partial(const float* __restrict__ x) {
    int idx = blockIdx.x * 256 + threadIdx.x;          // [0, B*T*N)
    int n  = idx & (NN - 1);
    int bt = idx >> 12;                                // b*T + t
    const float* p = x + (size_t)bt * CC * NN + n;
    float acc = 0.0f;
#pragma unroll
    for (int c = 0; c < CC; ++c) {
        float v = p[(size_t)c * NN];
        acc += v * v;
    }
    g_partial[idx] = sqrtf(acc);
}

// ---------------------------------------------------------------------------
// Kernel 2 (R2 form, verified): per-batch exact top-K -> mask bits.
// 1024 threads/block, 1 block/batch. 2-bit radix select with forced-bit
// skipping (block OR == AND) and one __syncthreads per active iteration.
// ---------------------------------------------------------------------------
__global__ void __launch_bounds__(1024, 1) k_select() {
    __shared__ unsigned long long s_acc[20];   // per-iteration packed counters
    __shared__ unsigned s_u32[66];             // OR/AND reduction
    __shared__ unsigned s_mask[NN / 32];       // 128 words
    __shared__ int s_scan[32];

    const int b    = blockIdx.x;
    const int j    = threadIdx.x;              // 0..1023
    const int lane = j & 31;
    const int wid  = j >> 5;

    // --- scores: 4 per thread, sequential over t (bit-exact order) ---
    const float4* part = (const float4*)g_partial;
    float s0 = 0.f, s1 = 0.f, s2 = 0.f, s3 = 0.f;
#pragma unroll
    for (int t = 0; t < TT; ++t) {
        float4 f = part[(size_t)(b * TT + t) * (NN / 4) + j];
        s0 += f.x; s1 += f.y; s2 += f.z; s3 += f.w;
    }
    const float inv = 1.0f / (float)TT;
    unsigned u0 = __float_as_uint(s0 * inv);
    unsigned u1 = __float_as_uint(s1 * inv);
    unsigned u2 = __float_as_uint(s2 * inv);
    unsigned u3 = __float_as_uint(s3 * inv);

    // --- init shared ---
    if (j < 20) s_acc[j] = 0ull;
    if (j < NN / 32) s_mask[j] = 0u;

    // --- block OR / AND of all score bits ---
    unsigned ov = u0 | u1 | u2 | u3;
    unsigned av = u0 & u1 & u2 & u3;
#pragma unroll
    for (int d = 16; d; d >>= 1) {
        ov |= __shfl_xor_sync(0xffffffffu, ov, d);
        av &= __shfl_xor_sync(0xffffffffu, av, d);
    }
    if (lane == 0) { s_u32[wid] = ov; s_u32[32 + wid] = av; }
    __syncthreads();
    if (wid == 0) {
        unsigned o2 = s_u32[lane], a2 = s_u32[32 + lane];
#pragma unroll
        for (int d = 16; d; d >>= 1) {
            o2 |= __shfl_xor_sync(0xffffffffu, o2, d);
            a2 &= __shfl_xor_sync(0xffffffffu, a2, d);
        }
        if (lane == 0) { s_u32[64] = o2; s_u32[65] = a2; }
    }
    __syncthreads();
    const unsigned orv  = s_u32[64];
    const unsigned andv = s_u32[65];
    const unsigned diff = orv ^ andv;

    // --- 2-bit radix select: largest thr with count(u >= thr) >= KSEL ---
    unsigned thr = 0u;
#pragma unroll
    for (int p = 15; p >= 0; --p) {
        unsigned m2 = 3u << (2 * p);
        if ((diff & m2) == 0u) {               // both bits forced (uniform)
            thr |= (andv & m2);
            continue;
        }
        unsigned c1 = thr | (1u << (2 * p));
        unsigned c2 = thr | (2u << (2 * p));
        unsigned c3 = thr | (3u << (2 * p));
        int n1 = (u0 >= c1) + (u1 >= c1) + (u2 >= c1) + (u3 >= c1);
        int n2 = (u0 >= c2) + (u1 >= c2) + (u2 >= c2) + (u3 >= c2);
        int n3 = (u0 >= c3) + (u1 >= c3) + (u2 >= c3) + (u3 >= c3);
        unsigned long long pk = (unsigned long long)n1
                              | ((unsigned long long)n2 << 20)
                              | ((unsigned long long)n3 << 40);
#pragma unroll
        for (int d = 16; d; d >>= 1) pk += __shfl_xor_sync(0xffffffffu, pk, d);
        if (lane == 0) atomicAdd(&s_acc[p], pk);
        __syncthreads();
        unsigned long long tot = s_acc[p];
        int N1 = (int)(tot & 0xFFFFFull);
        int N2 = (int)((tot >> 20) & 0xFFFFFull);
        int N3 = (int)((tot >> 40) & 0xFFFFFull);
        if      (N3 >= KSEL) thr = c3;
        else if (N2 >= KSEL) thr = c2;
        else if (N1 >= KSEL) thr = c1;
    }

    // --- strictly-greater count (ties admitted by lowest index) ---
    {
        int gt = (u0 > thr) + (u1 > thr) + (u2 > thr) + (u3 > thr);
        unsigned long long pk = (unsigned long long)gt;
#pragma unroll
        for (int d = 16; d; d >>= 1) pk += __shfl_xor_sync(0xffffffffu, pk, d);
        if (lane == 0) atomicAdd(&s_acc[16], pk);
        __syncthreads();
    }
    int n_greater = (int)(s_acc[16] & 0xFFFFFull);
    int need = KSEL - n_greater;

    // --- exclusive scan over threads of per-thread equal-count ---
    int e = (u0 == thr) + (u1 == thr) + (u2 == thr) + (u3 == thr);
    int v = e;
#pragma unroll
    for (int d = 1; d < 32; d <<= 1) {
        int t = __shfl_up_sync(0xffffffffu, v, d);
        if (lane >= d) v += t;
    }
    if (lane == 31) s_scan[wid] = v;
    __syncthreads();
    if (wid == 0) {
        int w = s_scan[lane];
#pragma unroll
        for (int d = 1; d < 32; d <<= 1) {
            int t = __shfl_up_sync(0xffffffffu, w, d);
            if (lane >= d) w += t;
        }
        s_scan[lane] = w;
    }
    __syncthreads();
    int excl = v - e + (wid ? s_scan[wid - 1] : 0);

    // --- mask nibble for n = 4j..4j+3 ---
    unsigned nib = 0;
    int r = excl;
    unsigned uu[4] = {u0, u1, u2, u3};
#pragma unroll
    for (int i = 0; i < 4; ++i) {
        if (uu[i] > thr) {
            nib |= 1u << i;
        } else if (uu[i] == thr) {
            if (r < need) nib |= 1u << i;
            ++r;
        }
    }
    atomicOr(&s_mask[j >> 3], nib << ((j & 7) * 4));
    __syncthreads();
    if (j < NN / 32) g_maskbits[b * (NN / 32) + j] = s_mask[j];
}

// ---------------------------------------------------------------------------
// Kernel 3 (R1 form): streaming masked copy, 1 float4 per thread, forward
// order, fully coalesced, plain stores. Mask array (4 KB) is L1-resident.
// ---------------------------------------------------------------------------
__global__ void __launch_bounds__(256) k_mask(const float4* __restrict__ x4,
                                              float4* __restrict__ o4) {
    unsigned i = blockIdx.x * 256 + threadIdx.x;   // [0, 8388608)
    int n4 = i & ((NN / 4) - 1);
    int b  = i >> 20;
    int n  = n4 << 2;
    unsigned mword = g_maskbits[(b << 7) + (n >> 5)];
    unsigned bits  = mword >> (n & 31);
    float4 v = x4[(size_t)i];
    v.x = (bits & 1u) ? v.x : 0.0f;
    v.y = (bits & 2u) ? v.y : 0.0f;
    v.z = (bits & 4u) ? v.z : 0.0f;
    v.w = (bits & 8u) ? v.w : 0.0f;
    o4[(size_t)i] = v;
}

// ---------------------------------------------------------------------------
extern "C" void kernel_launch(void* const* d_in, const int* in_sizes, int n_in,
                              void* d_out, int out_size) {
    const float* x = (const float*)d_in[0];
    float* out = (float*)d_out;

    // Kernel 1: B*T*N = 524288 threads
    k_partial<<<(BB * TT * NN) / 256, 256>>>(x);

    // Kernel 2: one 1024-thread block per batch
    k_select<<<BB, 1024>>>();

    // Kernel 3: 8388608 float4 elements, 1 per thread
    k_mask<<<(BB * TT * CC * NN / 4) / 256, 256>>>(
        (const float4*)x, (float4*)out);
}

// round 4
// speedup vs baseline: 1.1713x; 1.1437x over previous
#include <cuda_runtime.h>
#include <cuda_bf16.h>
#include <math.h>

// Problem constants (fixed by reference setup_inputs)
#define BB 8
#define TT 16
#define CC 64
#define NN 4096          // H*W
#define KSEL 2048        // keep_k = N*(1-0.5)

// Scratch (device globals — no allocation allowed)
__device__ float g_partial[BB * TT * NN];            // sqrt(sum_c x^2) per (b,t,n), 2 MB
__device__ unsigned g_maskbits[BB * (NN / 32)];      // 1 bit per (b,n), 4 KB

// ---------------------------------------------------------------------------
// Kernel 1 (R1 form, 24.9us measured): partial = sqrt(sum_c x[b,t,c,n]^2)
// ---------------------------------------------------------------------------
__global__ void __launch_bounds__(256) k_partial(const float* __restrict__ x) {
    int idx = blockIdx.x * 256 + threadIdx.x;          // [0, B*T*N)
    int n  = idx & (NN - 1);
    int bt = idx >> 12;                                // b*T + t
    const float* p = x + (size_t)bt * CC * NN + n;
    float acc = 0.0f;
#pragma unroll
    for (int c = 0; c < CC; ++c) {
        float v = p[(size_t)c * NN];
        acc += v * v;
    }
    g_partial[idx] = sqrtf(acc);
}

// ---------------------------------------------------------------------------
// Kernel 2: per-batch exact top-K -> mask bits. 1024 threads/block, 1 block
// per batch. 2-bit radix select, forced-bit-pair skip, ATOMIC-FREE packed
// reduction with double buffering: ONE __syncthreads per active iteration.
// ---------------------------------------------------------------------------
__device__ __forceinline__ int warp_sum_i(int v) {
#pragma unroll
    for (int d = 16; d; d >>= 1) v += __shfl_xor_sync(0xffffffffu, v, d);
    return v;
}
__device__ __forceinline__ unsigned long long warp_sum_u64(unsigned long long v) {
#pragma unroll
    for (int d = 16; d; d >>= 1) v += __shfl_xor_sync(0xffffffffu, v, d);
    return v;
}

__global__ void __launch_bounds__(1024, 1) k_select() {
    __shared__ unsigned long long s_red64[2][32];  // double-buffered per-warp counts
    __shared__ unsigned s_u32[66];                 // OR/AND reduction
    __shared__ unsigned s_mask[NN / 32];           // 128 words
    __shared__ int s_scan[32];
    __shared__ int s_int[1];

    const int b    = blockIdx.x;
    const int j    = threadIdx.x;              // 0..1023
    const int lane = j & 31;
    const int wid  = j >> 5;

    // --- scores: 4 per thread, sequential over t (bit-exact vs reference) ---
    const float4* part = (const float4*)g_partial;
    float s0 = 0.f, s1 = 0.f, s2 = 0.f, s3 = 0.f;
#pragma unroll
    for (int t = 0; t < TT; ++t) {
        float4 f = part[(size_t)(b * TT + t) * (NN / 4) + j];
        s0 += f.x; s1 += f.y; s2 += f.z; s3 += f.w;
    }
    const float inv = 1.0f / (float)TT;
    unsigned u0 = __float_as_uint(s0 * inv);
    unsigned u1 = __float_as_uint(s1 * inv);
    unsigned u2 = __float_as_uint(s2 * inv);
    unsigned u3 = __float_as_uint(s3 * inv);

    if (j < NN / 32) s_mask[j] = 0u;

    // --- block OR / AND of all score bits (2 barriers, once) ---
    unsigned ov = u0 | u1 | u2 | u3;
    unsigned av = u0 & u1 & u2 & u3;
#pragma unroll
    for (int d = 16; d; d >>= 1) {
        ov |= __shfl_xor_sync(0xffffffffu, ov, d);
        av &= __shfl_xor_sync(0xffffffffu, av, d);
    }
    if (lane == 0) { s_u32[wid] = ov; s_u32[32 + wid] = av; }
    __syncthreads();
    {
        unsigned o2 = s_u32[lane], a2 = s_u32[32 + lane];
#pragma unroll
        for (int d = 16; d; d >>= 1) {
            o2 |= __shfl_xor_sync(0xffffffffu, o2, d);
            a2 &= __shfl_xor_sync(0xffffffffu, a2, d);
        }
        if (j == 0) { s_u32[64] = o2; s_u32[65] = a2; }
    }
    __syncthreads();
    const unsigned orv  = s_u32[64];
    const unsigned andv = s_u32[65];
    const unsigned diff = orv ^ andv;

    // --- 2-bit radix select: largest thr with count(u >= thr) >= KSEL ---
    unsigned thr = 0u;
    int par = 0;
#pragma unroll
    for (int p = 15; p >= 0; --p) {
        unsigned m2 = 3u << (2 * p);
        if ((diff & m2) == 0u) {               // both bits uniform across block
            thr |= (andv & m2);
            continue;
        }
        unsigned c1 = thr | (1u << (2 * p));
        unsigned c2 = thr | (2u << (2 * p));
        unsigned c3 = thr | (3u << (2 * p));
        int n1 = (u0 >= c1) + (u1 >= c1) + (u2 >= c1) + (u3 >= c1);
        int n2 = (u0 >= c2) + (u1 >= c2) + (u2 >= c2) + (u3 >= c2);
        int n3 = (u0 >= c3) + (u1 >= c3) + (u2 >= c3) + (u3 >= c3);
        unsigned long long pk = (unsigned long long)n1
                              | ((unsigned long long)n2 << 20)
                              | ((unsigned long long)n3 << 40);
        pk = warp_sum_u64(pk);
        if (lane == 0) s_red64[par][wid] = pk;
        __syncthreads();
        // every warp redundantly reduces the 32 per-warp partials (no 2nd barrier;
        // double buffering makes the next iteration's overwrite safe)
        unsigned long long tot = warp_sum_u64(s_red64[par][lane]);
        int N1 = (int)(tot & 0xFFFFFull);
        int N2 = (int)((tot >> 20) & 0xFFFFFull);
        int N3 = (int)((tot >> 40) & 0xFFFFFull);
        if      (N3 >= KSEL) thr = c3;
        else if (N2 >= KSEL) thr = c2;
        else if (N1 >= KSEL) thr = c1;
        par ^= 1;
    }
    __syncthreads();   // protect s_red64 before reuse below

    // --- strictly-greater count (ties admitted by lowest index) ---
    {
        unsigned long long pk =
            (unsigned long long)((u0 > thr) + (u1 > thr) + (u2 > thr) + (u3 > thr));
        pk = warp_sum_u64(pk);
        if (lane == 0) s_red64[0][wid] = pk;
        __syncthreads();
        unsigned long long tot = warp_sum_u64(s_red64[0][lane]);
        if (j == 0) s_int[0] = (int)tot;
        __syncthreads();
    }
    int need = KSEL - s_int[0];

    // --- exclusive scan over threads of per-thread equal-count ---
    int e = (u0 == thr) + (u1 == thr) + (u2 == thr) + (u3 == thr);
    int v = e;
#pragma unroll
    for (int d = 1; d < 32; d <<= 1) {
        int t = __shfl_up_sync(0xffffffffu, v, d);
        if (lane >= d) v += t;
    }
    if (lane == 31) s_scan[wid] = v;
    __syncthreads();
    if (wid == 0) {
        int w = s_scan[lane];
#pragma unroll
        for (int d = 1; d < 32; d <<= 1) {
            int t = __shfl_up_sync(0xffffffffu, w, d);
            if (lane >= d) w += t;
        }
        s_scan[lane] = w;
    }
    __syncthreads();
    int excl = v - e + (wid ? s_scan[wid - 1] : 0);

    // --- mask nibble for n = 4j..4j+3 ---
    unsigned nib = 0;
    int r = excl;
    unsigned uu[4] = {u0, u1, u2, u3};
#pragma unroll
    for (int i = 0; i < 4; ++i) {
        if (uu[i] > thr) {
            nib |= 1u << i;
        } else if (uu[i] == thr) {
            if (r < need) nib |= 1u << i;
            ++r;
        }
    }
    atomicOr(&s_mask[j >> 3], nib << ((j & 7) * 4));
    __syncthreads();
    if (j < NN / 32) g_maskbits[b * (NN / 32) + j] = s_mask[j];
}

// ---------------------------------------------------------------------------
// Kernel 3 (R1 form, ~50us measured): streaming masked copy, 1 float4 per
// thread, forward order, fully coalesced, plain stores.
// ---------------------------------------------------------------------------
__global__ void __launch_bounds__(256) k_mask(const float4* __restrict__ x4,
                                              float4* __restrict__ o4) {
    unsigned i = blockIdx.x * 256 + threadIdx.x;   // [0, 8388608)
    int n4 = i & ((NN / 4) - 1);
    int b  = i >> 20;
    int n  = n4 << 2;
    unsigned mword = g_maskbits[(b << 7) + (n >> 5)];
    unsigned bits  = mword >> (n & 31);
    float4 v = x4[(size_t)i];
    v.x = (bits & 1u) ? v.x : 0.0f;
    v.y = (bits & 2u) ? v.y : 0.0f;
    v.z = (bits & 4u) ? v.z : 0.0f;
    v.w = (bits & 8u) ? v.w : 0.0f;
    o4[(size_t)i] = v;
}

// ---------------------------------------------------------------------------
extern "C" void kernel_launch(void* const* d_in, const int* in_sizes, int n_in,
                              void* d_out, int out_size) {
    const float* x = (const float*)d_in[0];
    float* out = (float*)d_out;

    // Kernel 1: B*T*N = 524288 threads
    k_partial<<<(BB * TT * NN) / 256, 256>>>(x);

    // Kernel 2: one 1024-thread block per batch
    k_select<<<BB, 1024>>>();

    // Kernel 3: 8388608 float4 elements, 1 per thread
    k_mask<<<(BB * TT * CC * NN / 4) / 256, 256>>>(
        (const float4*)x, (float4*)out);
}

// round 5
// speedup vs baseline: 1.2699x; 1.0842x over previous
#include <cuda_runtime.h>
#include <cuda_bf16.h>
#include <math.h>

// Problem constants (fixed by reference setup_inputs)
#define BB 8
#define TT 16
#define CC 64
#define NN 4096          // H*W
#define KSEL 2048        // keep_k = N*(1-0.5)

// Scratch (device globals — no allocation allowed)
__device__ float g_partial[BB * TT * NN];            // sqrt(sum_c x^2) per (b,t,n), 2 MB
__device__ unsigned g_maskbits[BB * (NN / 32)];      // 1 bit per (b,n), 4 KB

// ---------------------------------------------------------------------------
// Kernel 1 (R1 form, 24.4us measured): partial = sqrt(sum_c x[b,t,c,n]^2)
// ---------------------------------------------------------------------------
__global__ void __launch_bounds__(256) k_partial(const float* __restrict__ x) {
    int idx = blockIdx.x * 256 + threadIdx.x;          // [0, B*T*N)
    int n  = idx & (NN - 1);
    int bt = idx >> 12;                                // b*T + t
    const float* p = x + (size_t)bt * CC * NN + n;
    float acc = 0.0f;
#pragma unroll
    for (int c = 0; c < CC; ++c) {
        float v = p[(size_t)c * NN];
        acc += v * v;
    }
    g_partial[idx] = sqrtf(acc);
}

// ---------------------------------------------------------------------------
// Kernel 2 (R4 form, verified): per-batch exact top-K -> mask bits.
// Atomic-free 2-bit radix select, forced-bit-pair skip, 1 barrier/iteration.
// ---------------------------------------------------------------------------
__device__ __forceinline__ unsigned long long warp_sum_u64(unsigned long long v) {
#pragma unroll
    for (int d = 16; d; d >>= 1) v += __shfl_xor_sync(0xffffffffu, v, d);
    return v;
}

__global__ void __launch_bounds__(1024, 1) k_select() {
    __shared__ unsigned long long s_red64[2][32];  // double-buffered per-warp counts
    __shared__ unsigned s_u32[66];                 // OR/AND reduction
    __shared__ unsigned s_mask[NN / 32];           // 128 words
    __shared__ int s_scan[32];
    __shared__ int s_int[1];

    const int b    = blockIdx.x;
    const int j    = threadIdx.x;              // 0..1023
    const int lane = j & 31;
    const int wid  = j >> 5;

    // --- scores: 4 per thread, sequential over t (bit-exact vs reference) ---
    const float4* part = (const float4*)g_partial;
    float s0 = 0.f, s1 = 0.f, s2 = 0.f, s3 = 0.f;
#pragma unroll
    for (int t = 0; t < TT; ++t) {
        float4 f = part[(size_t)(b * TT + t) * (NN / 4) + j];
        s0 += f.x; s1 += f.y; s2 += f.z; s3 += f.w;
    }
    const float inv = 1.0f / (float)TT;
    unsigned u0 = __float_as_uint(s0 * inv);
    unsigned u1 = __float_as_uint(s1 * inv);
    unsigned u2 = __float_as_uint(s2 * inv);
    unsigned u3 = __float_as_uint(s3 * inv);

    if (j < NN / 32) s_mask[j] = 0u;

    // --- block OR / AND of all score bits ---
    unsigned ov = u0 | u1 | u2 | u3;
    unsigned av = u0 & u1 & u2 & u3;
#pragma unroll
    for (int d = 16; d; d >>= 1) {
        ov |= __shfl_xor_sync(0xffffffffu, ov, d);
        av &= __shfl_xor_sync(0xffffffffu, av, d);
    }
    if (lane == 0) { s_u32[wid] = ov; s_u32[32 + wid] = av; }
    __syncthreads();
    {
        unsigned o2 = s_u32[lane], a2 = s_u32[32 + lane];
#pragma unroll
        for (int d = 16; d; d >>= 1) {
            o2 |= __shfl_xor_sync(0xffffffffu, o2, d);
            a2 &= __shfl_xor_sync(0xffffffffu, a2, d);
        }
        if (j == 0) { s_u32[64] = o2; s_u32[65] = a2; }
    }
    __syncthreads();
    const unsigned orv  = s_u32[64];
    const unsigned andv = s_u32[65];
    const unsigned diff = orv ^ andv;

    // --- 2-bit radix select: largest thr with count(u >= thr) >= KSEL ---
    unsigned thr = 0u;
    int par = 0;
#pragma unroll
    for (int p = 15; p >= 0; --p) {
        unsigned m2 = 3u << (2 * p);
        if ((diff & m2) == 0u) {               // both bits uniform across block
            thr |= (andv & m2);
            continue;
        }
        unsigned c1 = thr | (1u << (2 * p));
        unsigned c2 = thr | (2u << (2 * p));
        unsigned c3 = thr | (3u << (2 * p));
        int n1 = (u0 >= c1) + (u1 >= c1) + (u2 >= c1) + (u3 >= c1);
        int n2 = (u0 >= c2) + (u1 >= c2) + (u2 >= c2) + (u3 >= c2);
        int n3 = (u0 >= c3) + (u1 >= c3) + (u2 >= c3) + (u3 >= c3);
        unsigned long long pk = (unsigned long long)n1
                              | ((unsigned long long)n2 << 20)
                              | ((unsigned long long)n3 << 40);
        pk = warp_sum_u64(pk);
        if (lane == 0) s_red64[par][wid] = pk;
        __syncthreads();
        unsigned long long tot = warp_sum_u64(s_red64[par][lane]);
        int N1 = (int)(tot & 0xFFFFFull);
        int N2 = (int)((tot >> 20) & 0xFFFFFull);
        int N3 = (int)((tot >> 40) & 0xFFFFFull);
        if      (N3 >= KSEL) thr = c3;
        else if (N2 >= KSEL) thr = c2;
        else if (N1 >= KSEL) thr = c1;
        par ^= 1;
    }
    __syncthreads();   // protect s_red64 before reuse below

    // --- strictly-greater count (ties admitted by lowest index) ---
    {
        unsigned long long pk =
            (unsigned long long)((u0 > thr) + (u1 > thr) + (u2 > thr) + (u3 > thr));
        pk = warp_sum_u64(pk);
        if (lane == 0) s_red64[0][wid] = pk;
        __syncthreads();
        unsigned long long tot = warp_sum_u64(s_red64[0][lane]);
        if (j == 0) s_int[0] = (int)tot;
        __syncthreads();
    }
    int need = KSEL - s_int[0];

    // --- exclusive scan over threads of per-thread equal-count ---
    int e = (u0 == thr) + (u1 == thr) + (u2 == thr) + (u3 == thr);
    int v = e;
#pragma unroll
    for (int d = 1; d < 32; d <<= 1) {
        int t = __shfl_up_sync(0xffffffffu, v, d);
        if (lane >= d) v += t;
    }
    if (lane == 31) s_scan[wid] = v;
    __syncthreads();
    if (wid == 0) {
        int w = s_scan[lane];
#pragma unroll
        for (int d = 1; d < 32; d <<= 1) {
            int t = __shfl_up_sync(0xffffffffu, w, d);
            if (lane >= d) w += t;
        }
        s_scan[lane] = w;
    }
    __syncthreads();
    int excl = v - e + (wid ? s_scan[wid - 1] : 0);

    // --- mask nibble for n = 4j..4j+3 ---
    unsigned nib = 0;
    int r = excl;
    unsigned uu[4] = {u0, u1, u2, u3};
#pragma unroll
    for (int i = 0; i < 4; ++i) {
        if (uu[i] > thr) {
            nib |= 1u << i;
        } else if (uu[i] == thr) {
            if (r < need) nib |= 1u << i;
            ++r;
        }
    }
    atomicOr(&s_mask[j >> 3], nib << ((j & 7) * 4));
    __syncthreads();
    if (j < NN / 32) g_maskbits[b * (NN / 32) + j] = s_mask[j];
}

// ---------------------------------------------------------------------------
// Kernel 3: R1 body (1 float4/thread, fully coalesced) with L2-residue
// harvesting: REVERSE block order (touch k_partial's freshest lines first),
// __ldcs reads (misses insert evict-first, don't displace residue),
// __stcs writes (output stream doesn't flush residue).
// ---------------------------------------------------------------------------
__global__ void __launch_bounds__(256) k_mask(const float4* __restrict__ x4,
                                              float4* __restrict__ o4) {
    unsigned blk = gridDim.x - 1 - blockIdx.x;     // reverse traversal
    unsigned i = blk * 256 + threadIdx.x;          // [0, 8388608)
    int n4 = i & ((NN / 4) - 1);
    int b  = i >> 20;
    int n  = n4 << 2;
    unsigned mword = g_maskbits[(b << 7) + (n >> 5)];
    unsigned bits  = mword >> (n & 31);
    float4 v = __ldcs(&x4[(size_t)i]);
    v.x = (bits & 1u) ? v.x : 0.0f;
    v.y = (bits & 2u) ? v.y : 0.0f;
    v.z = (bits & 4u) ? v.z : 0.0f;
    v.w = (bits & 8u) ? v.w : 0.0f;
    __stcs(&o4[(size_t)i], v);
}

// ---------------------------------------------------------------------------
extern "C" void kernel_launch(void* const* d_in, const int* in_sizes, int n_in,
                              void* d_out, int out_size) {
    const float* x = (const float*)d_in[0];
    float* out = (float*)d_out;

    // Kernel 1: B*T*N = 524288 threads
    k_partial<<<(BB * TT * NN) / 256, 256>>>(x);

    // Kernel 2: one 1024-thread block per batch
    k_select<<<BB, 1024>>>();

    // Kernel 3: 8388608 float4 elements, 1 per thread
    k_mask<<<(BB * TT * CC * NN / 4) / 256, 256>>>(
        (const float4*)x, (float4*)out);
}